// round 1
// baseline (speedup 1.0000x reference)
#include <cuda_runtime.h>
#include <math_constants.h>

// Problem constants
#define N_BATCH 4
#define C_CH    128
#define S_FR    31
#define HW      704           // 32*22
#define NS      120           // 4*(31-1)
#define NPIX    87296         // 4*31*704
#define TOPK    16
#define LOG2E   1.4426950408889634f

// Scratch (device globals — no allocation allowed)
__device__ float g_X0[NS * HW];     // a values (e-domain, fine)
__device__ float g_BL[NS * HW];     // b * log2e  (order-preserving)
__device__ float g_TB[NS * 32];     // per row: [0..15] top desc, [16..31] bottom asc (bl-domain)

__device__ __forceinline__ float ex2(float x) {
    float r;
    asm("ex2.approx.f32 %0, %1;" : "=f"(r) : "f"(x));
    return r;
}

// ---------------------------------------------------------------------------
// Kernel A: per-pixel channel contraction. One pass over x (read once),
// produces both X0 (pairs 0..29 with w1,b1) and BL (pairs from frame f>=1
// with w2,b2, pre-scaled by log2e).
// ---------------------------------------------------------------------------
__global__ void kA(const float* __restrict__ x,
                   const float* __restrict__ w1, const float* __restrict__ b1,
                   const float* __restrict__ w2, const float* __restrict__ b2) {
    __shared__ float sw1[C_CH], sw2[C_CH];
    int tid = threadIdx.x;
    if (tid < C_CH) { sw1[tid] = w1[tid]; sw2[tid] = w2[tid]; }
    __syncthreads();

    int p = blockIdx.x * blockDim.x + tid;
    if (p >= NPIX) return;
    int n = p / (S_FR * HW);              // 21824 per n
    int q = p - n * (S_FR * HW);
    int f = q / HW;
    int i = q - f * HW;

    const float* xp = x + (size_t)n * (C_CH * S_FR * HW) + q;
    float y1 = 0.f, y2 = 0.f;
#pragma unroll 8
    for (int c = 0; c < C_CH; c++) {
        float v = xp[c * (S_FR * HW)];
        y1 = fmaf(v, sw1[c], y1);
        y2 = fmaf(v, sw2[c], y2);
    }
    if (f < S_FR - 1) g_X0[(n * (S_FR - 1) + f) * HW + i] = y1 + b1[0];
    if (f >= 1)       g_BL[(n * (S_FR - 1) + f - 1) * HW + i] = (y2 + b2[0]) * LOG2E;
}

// ---------------------------------------------------------------------------
// Kernel B: per row, find top-16 (desc) and bottom-16 (asc) of BL.
// One warp per row, iterative max/min with consumption.
// ---------------------------------------------------------------------------
__global__ void kB() {
    int r = blockIdx.x;
    int lane = threadIdx.x;   // 32 threads
    __shared__ float sv[HW];

    for (int j = lane; j < HW; j += 32) sv[j] = g_BL[r * HW + j];
    __syncwarp();

    // top-16 descending
    for (int it = 0; it < TOPK; it++) {
        float lm = -CUDART_INF_F; int li = 0;
        for (int j = lane; j < HW; j += 32) {
            float v = sv[j];
            if (v > lm) { lm = v; li = j; }
        }
        for (int o = 16; o > 0; o >>= 1) {
            float ov = __shfl_down_sync(0xffffffff, lm, o);
            int   oi = __shfl_down_sync(0xffffffff, li, o);
            if (ov > lm) { lm = ov; li = oi; }
        }
        lm = __shfl_sync(0xffffffff, lm, 0);
        li = __shfl_sync(0xffffffff, li, 0);
        if (lane == 0) { g_TB[r * 32 + it] = lm; sv[li] = -CUDART_INF_F; }
        __syncwarp();
    }

    // restore and do bottom-16 ascending
    for (int j = lane; j < HW; j += 32) sv[j] = g_BL[r * HW + j];
    __syncwarp();
    for (int it = 0; it < TOPK; it++) {
        float lm = CUDART_INF_F; int li = 0;
        for (int j = lane; j < HW; j += 32) {
            float v = sv[j];
            if (v < lm) { lm = v; li = j; }
        }
        for (int o = 16; o > 0; o >>= 1) {
            float ov = __shfl_down_sync(0xffffffff, lm, o);
            int   oi = __shfl_down_sync(0xffffffff, li, o);
            if (ov < lm) { lm = ov; li = oi; }
        }
        lm = __shfl_sync(0xffffffff, lm, 0);
        li = __shfl_sync(0xffffffff, li, 0);
        if (lane == 0) { g_TB[r * 32 + 16 + it] = lm; sv[li] = CUDART_INF_F; }
        __syncwarp();
    }
}

// ---------------------------------------------------------------------------
// Kernel C: main softmax-denominator + top-k emit.
// Grid: 2 chunks per row (240 blocks), 352 threads; thread <-> one i.
// Denominator: D = sum_j exp2(a*bl_j - msc2); numerators from selected bl's.
// Output: 16 consecutive floats per i (since 704 = 16*44 -> k2 = i/44).
// ---------------------------------------------------------------------------
__global__ void kC(float* __restrict__ out) {
    __shared__ __align__(16) float s_bl[HW];
    __shared__ float s_sel[32];
    int r = blockIdx.x >> 1;
    int chunk = blockIdx.x & 1;
    int tid = threadIdx.x;   // 352

    for (int j = tid; j < HW; j += 352) s_bl[j] = g_BL[r * HW + j];
    if (tid < 32) s_sel[tid] = g_TB[r * 32 + tid];
    __syncthreads();

    int i = chunk * 352 + tid;
    float a = g_X0[r * HW + i];
    // max score (exp2 domain): a>=0 -> a*blmax ; a<0 -> a*blmin
    float msc = (a >= 0.f) ? a * s_sel[0] : a * s_sel[16];
    float nm = -msc;

    float d0 = 0.f, d1 = 0.f, d2 = 0.f, d3 = 0.f;
#pragma unroll 4
    for (int j = 0; j < HW; j += 4) {
        float4 b4 = *reinterpret_cast<const float4*>(&s_bl[j]);
        d0 += ex2(fmaf(a, b4.x, nm));
        d1 += ex2(fmaf(a, b4.y, nm));
        d2 += ex2(fmaf(a, b4.z, nm));
        d3 += ex2(fmaf(a, b4.w, nm));
    }
    float rD = __frcp_rn((d0 + d1) + (d2 + d3));

    const float* sel = (a >= 0.f) ? s_sel : (s_sel + 16);
    float v[TOPK];
#pragma unroll
    for (int k = 0; k < TOPK; k++)
        v[k] = ex2(fmaf(a, sel[k], nm)) * rD;

    // output indexing: idx = i*16 + k ; k2 = i/44 (k-independent), rem = (i%44)*16 + k
    int n  = r / (S_FR - 1);
    int sp = r - n * (S_FR - 1);
    int k2 = i / 44;
    int im = i - k2 * 44;
    float4* o = reinterpret_cast<float4*>(
        out + ((size_t)((n * TOPK + k2) * (S_FR - 1) + sp)) * HW + im * 16);
    o[0] = make_float4(v[0],  v[1],  v[2],  v[3]);
    o[1] = make_float4(v[4],  v[5],  v[6],  v[7]);
    o[2] = make_float4(v[8],  v[9],  v[10], v[11]);
    o[3] = make_float4(v[12], v[13], v[14], v[15]);
}

// ---------------------------------------------------------------------------
extern "C" void kernel_launch(void* const* d_in, const int* in_sizes, int n_in,
                              void* d_out, int out_size) {
    const float* x  = (const float*)d_in[0];
    const float* w1 = (const float*)d_in[1];
    const float* b1 = (const float*)d_in[2];
    const float* w2 = (const float*)d_in[3];
    const float* b2 = (const float*)d_in[4];
    float* out = (float*)d_out;

    kA<<<(NPIX + 255) / 256, 256>>>(x, w1, b1, w2, b2);
    kB<<<NS, 32>>>();
    kC<<<NS * 2, 352>>>(out);
}

// round 2
// speedup vs baseline: 1.0433x; 1.0433x over previous
#include <cuda_runtime.h>
#include <math_constants.h>

// Problem constants
#define N_BATCH 4
#define C_CH    128
#define S_FR    31
#define HW      704           // 32*22
#define NS      120           // 4*(31-1)
#define NPIX    87296         // 4*31*704
#define TOPK    16
#define LOG2E   1.4426950408889634f

// Scratch (device globals — no allocation allowed)
__device__ float g_X0[NS * HW];     // a values (e-domain)
__device__ float g_BL[NS * HW];     // b * log2e  (order-preserving)
__device__ float g_TB[NS * 32];     // per row: [0..15] top desc, [16..31] bottom asc

__device__ __forceinline__ float ex2(float x) {
    float r;
    asm("ex2.approx.f32 %0, %1;" : "=f"(r) : "f"(x));
    return r;
}

// ---------------------------------------------------------------------------
// Kernel A: per-pixel channel contraction, one pass over x.
// 128-thread blocks, explicit 16-wide load batches for deep MLP.
// ---------------------------------------------------------------------------
__global__ void kA(const float* __restrict__ x,
                   const float* __restrict__ w1, const float* __restrict__ b1,
                   const float* __restrict__ w2, const float* __restrict__ b2) {
    __shared__ float sw1[C_CH], sw2[C_CH];
    int tid = threadIdx.x;   // 128
    sw1[tid] = w1[tid];
    sw2[tid] = w2[tid];
    __syncthreads();

    int p = blockIdx.x * 128 + tid;
    if (p >= NPIX) return;
    int n = p / (S_FR * HW);
    int q = p - n * (S_FR * HW);
    int f = q / HW;
    int i = q - f * HW;

    const float* xp = x + (size_t)n * (C_CH * S_FR * HW) + q;
    float y1a = 0.f, y1b = 0.f, y2a = 0.f, y2b = 0.f;
#pragma unroll
    for (int cb = 0; cb < C_CH; cb += 16) {
        float v[16];
#pragma unroll
        for (int u = 0; u < 16; u++) v[u] = xp[(cb + u) * (S_FR * HW)];
#pragma unroll
        for (int u = 0; u < 16; u += 2) {
            y1a = fmaf(v[u],     sw1[cb + u],     y1a);
            y2a = fmaf(v[u],     sw2[cb + u],     y2a);
            y1b = fmaf(v[u + 1], sw1[cb + u + 1], y1b);
            y2b = fmaf(v[u + 1], sw2[cb + u + 1], y2b);
        }
    }
    float y1 = y1a + y1b, y2 = y2a + y2b;
    if (f < S_FR - 1) g_X0[(n * (S_FR - 1) + f) * HW + i] = y1 + b1[0];
    if (f >= 1)       g_BL[(n * (S_FR - 1) + f - 1) * HW + i] = (y2 + b2[0]) * LOG2E;
}

// ---------------------------------------------------------------------------
// Kernel B: per-row bitonic sort (704 padded to 1024 with +inf, ascending).
// Sorted both-ends give top-16 desc and bottom-16 asc. 512 thr/block, 120 blocks.
// ---------------------------------------------------------------------------
__global__ void kB() {
    __shared__ float s[1024];
    int r = blockIdx.x;
    int tid = threadIdx.x;   // 512

    for (int idx = tid; idx < 1024; idx += 512)
        s[idx] = (idx < HW) ? g_BL[r * HW + idx] : CUDART_INF_F;
    __syncthreads();

    for (int k = 2; k <= 1024; k <<= 1) {
        for (int j = k >> 1; j > 0; j >>= 1) {
            for (int i = tid; i < 1024; i += 512) {
                int ixj = i ^ j;
                if (ixj > i) {
                    float a = s[i], b = s[ixj];
                    bool up = ((i & k) == 0);          // ascending subsequence
                    if ((a > b) == up) { s[i] = b; s[ixj] = a; }
                }
            }
            __syncthreads();
        }
    }

    // s[0..703] sorted ascending, s[704..1023] = +inf
    if (tid < TOPK)            g_TB[r * 32 + tid]      = s[HW - 1 - tid];  // top desc
    else if (tid < 2 * TOPK)   g_TB[r * 32 + tid]      = s[tid - TOPK];    // bottom asc
}

// ---------------------------------------------------------------------------
// Kernel C: softmax denominator + top-k emit.
// 11 chunks of 64 pixels per row -> 1320 small blocks for dynamic balance.
// ---------------------------------------------------------------------------
__global__ void kC(float* __restrict__ out) {
    __shared__ __align__(16) float s_bl[HW];
    __shared__ float s_sel[32];
    int r = blockIdx.x / 11;
    int chunk = blockIdx.x - r * 11;
    int tid = threadIdx.x;   // 64

    {
        const float4* src = reinterpret_cast<const float4*>(g_BL + r * HW);
        float4* dst = reinterpret_cast<float4*>(s_bl);
#pragma unroll
        for (int j = tid; j < HW / 4; j += 64) dst[j] = src[j];
    }
    if (tid < 32) s_sel[tid] = g_TB[r * 32 + tid];
    __syncthreads();

    int i = chunk * 64 + tid;
    float a = g_X0[r * HW + i];
    float msc = (a >= 0.f) ? a * s_sel[0] : a * s_sel[16];
    float nm = -msc;

    float d0 = 0.f, d1 = 0.f, d2 = 0.f, d3 = 0.f;
#pragma unroll 4
    for (int j = 0; j < HW; j += 4) {
        float4 b4 = *reinterpret_cast<const float4*>(&s_bl[j]);
        d0 += ex2(fmaf(a, b4.x, nm));
        d1 += ex2(fmaf(a, b4.y, nm));
        d2 += ex2(fmaf(a, b4.z, nm));
        d3 += ex2(fmaf(a, b4.w, nm));
    }
    float rD = __frcp_rn((d0 + d1) + (d2 + d3));

    const float* sel = (a >= 0.f) ? s_sel : (s_sel + 16);
    float v[TOPK];
#pragma unroll
    for (int k = 0; k < TOPK; k++)
        v[k] = ex2(fmaf(a, sel[k], nm)) * rD;

    // output: idx = i*16 + k ; k2 = i/44 (k-independent), rem = (i%44)*16 + k
    int n  = r / (S_FR - 1);
    int sp = r - n * (S_FR - 1);
    int k2 = i / 44;
    int im = i - k2 * 44;
    float4* o = reinterpret_cast<float4*>(
        out + ((size_t)((n * TOPK + k2) * (S_FR - 1) + sp)) * HW + im * 16);
    o[0] = make_float4(v[0],  v[1],  v[2],  v[3]);
    o[1] = make_float4(v[4],  v[5],  v[6],  v[7]);
    o[2] = make_float4(v[8],  v[9],  v[10], v[11]);
    o[3] = make_float4(v[12], v[13], v[14], v[15]);
}

// ---------------------------------------------------------------------------
extern "C" void kernel_launch(void* const* d_in, const int* in_sizes, int n_in,
                              void* d_out, int out_size) {
    const float* x  = (const float*)d_in[0];
    const float* w1 = (const float*)d_in[1];
    const float* b1 = (const float*)d_in[2];
    const float* w2 = (const float*)d_in[3];
    const float* b2 = (const float*)d_in[4];
    float* out = (float*)d_out;

    kA<<<NPIX / 128, 128>>>(x, w1, b1, w2, b2);
    kB<<<NS, 512>>>();
    kC<<<NS * 11, 64>>>(out);
}

// round 3
// speedup vs baseline: 1.6800x; 1.6104x over previous
#include <cuda_runtime.h>
#include <math_constants.h>

// Problem constants
#define N_BATCH 4
#define C_CH    128
#define S_FR    31
#define HW      704           // 32*22
#define NS      120           // 4*(31-1)
#define NPIX    87296         // 4*31*704 (= 64*1364)
#define TOPK    16
#define NB      128           // denominator bins (power of 2)
#define LOG2E   1.4426950408889634f
#define LN2F    0.6931471805599453f

// Scratch (device globals — no allocation allowed)
__device__ float  g_X0[NS * HW];        // a values
__device__ float  g_BL[NS * HW];        // b * log2e (order-preserving)
__device__ float  g_TB[NS * 32];        // [0..15] top desc, [16..31] bottom asc
__device__ float4 g_BINS[NS * NB];      // per row: (S0, S1, S2/2, S3/6) per bin
__device__ float2 g_ROW[NS];            // per row: (lo, W)

__device__ __forceinline__ float ex2(float x) {
    float r;
    asm("ex2.approx.f32 %0, %1;" : "=f"(r) : "f"(x));
    return r;
}

// ---------------------------------------------------------------------------
// Kernel A: channel contraction, 2 threads per pixel (split-C) for 2x warps.
// Block: 128 threads = 64 pixels x 2 channel halves.
// ---------------------------------------------------------------------------
__global__ void kA(const float* __restrict__ x,
                   const float* __restrict__ w1, const float* __restrict__ b1,
                   const float* __restrict__ w2, const float* __restrict__ b2) {
    __shared__ float sw1[C_CH], sw2[C_CH];
    __shared__ float r1s[64], r2s[64];
    int tid = threadIdx.x;          // 0..127
    sw1[tid] = w1[tid];
    sw2[tid] = w2[tid];
    __syncthreads();

    int half = tid >> 6;            // 0 or 1
    int px   = tid & 63;
    int p = blockIdx.x * 64 + px;   // NPIX = 64*1364 exactly
    int n = p / (S_FR * HW);
    int q = p - n * (S_FR * HW);
    int f = q / HW;
    int i = q - f * HW;

    const float* xp = x + (size_t)n * (C_CH * S_FR * HW)
                        + (size_t)(half * 64) * (S_FR * HW) + q;
    const float* pw1 = sw1 + half * 64;
    const float* pw2 = sw2 + half * 64;

    float y1a = 0.f, y1b = 0.f, y2a = 0.f, y2b = 0.f;
#pragma unroll
    for (int cb = 0; cb < 64; cb += 16) {
        float v[16];
#pragma unroll
        for (int u = 0; u < 16; u++) v[u] = xp[(cb + u) * (S_FR * HW)];
#pragma unroll
        for (int u = 0; u < 16; u += 2) {
            y1a = fmaf(v[u],     pw1[cb + u],     y1a);
            y2a = fmaf(v[u],     pw2[cb + u],     y2a);
            y1b = fmaf(v[u + 1], pw1[cb + u + 1], y1b);
            y2b = fmaf(v[u + 1], pw2[cb + u + 1], y2b);
        }
    }
    float y1 = y1a + y1b, y2 = y2a + y2b;

    if (half == 1) { r1s[px] = y1; r2s[px] = y2; }
    __syncthreads();
    if (half == 0) {
        y1 += r1s[px];
        y2 += r2s[px];
        if (f < S_FR - 1) g_X0[(n * (S_FR - 1) + f) * HW + i] = y1 + b1[0];
        if (f >= 1)       g_BL[(n * (S_FR - 1) + f - 1) * HW + i] = (y2 + b2[0]) * LOG2E;
    }
}

// ---------------------------------------------------------------------------
// Kernel B: per-row bitonic sort (top/bottom-16 + lo/hi), then build 128
// equal-width bins with moments (count, Sd, Sd^2/2, Sd^3/6) via smem atomics.
// ---------------------------------------------------------------------------
__global__ void kB() {
    __shared__ float s[1024];
    __shared__ float binsm[NB * 4];
    __shared__ float s_lo, s_W, s_invW;
    int r = blockIdx.x;
    int tid = threadIdx.x;   // 512

    for (int idx = tid; idx < 1024; idx += 512)
        s[idx] = (idx < HW) ? g_BL[r * HW + idx] : CUDART_INF_F;
    if (tid < NB) {
        binsm[tid * 4 + 0] = 0.f; binsm[tid * 4 + 1] = 0.f;
        binsm[tid * 4 + 2] = 0.f; binsm[tid * 4 + 3] = 0.f;
    }
    __syncthreads();

    for (int k = 2; k <= 1024; k <<= 1) {
        for (int j = k >> 1; j > 0; j >>= 1) {
            int i = tid;
            {
                int ixj = i ^ j;
                if (ixj > i) {
                    float a = s[i], b = s[ixj];
                    bool up = ((i & k) == 0);
                    if ((a > b) == up) { s[i] = b; s[ixj] = a; }
                }
            }
            i = tid + 512;
            {
                int ixj = i ^ j;
                if (ixj > i) {
                    float a = s[i], b = s[ixj];
                    bool up = ((i & k) == 0);
                    if ((a > b) == up) { s[i] = b; s[ixj] = a; }
                }
            }
            __syncthreads();
        }
    }

    // s[0..703] sorted ascending
    if (tid < TOPK)          g_TB[r * 32 + tid] = s[HW - 1 - tid];   // top desc
    else if (tid < 2 * TOPK) g_TB[r * 32 + tid] = s[tid - TOPK];     // bottom asc
    if (tid == 0) {
        float lo = s[0], hi = s[HW - 1];
        float W = (hi - lo) * (1.0f / NB) + 1e-30f;
        s_lo = lo; s_W = W; s_invW = 1.0f / W;
        g_ROW[r] = make_float2(lo, W);
    }
    __syncthreads();

    float lo = s_lo, W = s_W, invW = s_invW;
    // bin from unsorted order (random -> spread atomics)
    for (int j = tid; j < HW; j += 512) {
        float v = g_BL[r * HW + j];
        int m = (int)((v - lo) * invW);
        m = (m > NB - 1) ? NB - 1 : (m < 0 ? 0 : m);
        float d = v - fmaf((float)m + 0.5f, W, lo);
        atomicAdd(&binsm[m * 4 + 0], 1.0f);
        atomicAdd(&binsm[m * 4 + 1], d);
        atomicAdd(&binsm[m * 4 + 2], 0.5f * d * d);
        atomicAdd(&binsm[m * 4 + 3], (1.0f / 6.0f) * d * d * d);
    }
    __syncthreads();
    if (tid < NB)
        g_BINS[r * NB + tid] = reinterpret_cast<float4*>(binsm)[tid];
}

// ---------------------------------------------------------------------------
// Kernel C: denominator via geometric-chain over bins (FMA pipe, ~2 MUFU/i),
// then exact top-k numerators. 11 chunks of 64 pixels per row.
// ---------------------------------------------------------------------------
__global__ void kC(float* __restrict__ out) {
    __shared__ float4 sb[NB];
    __shared__ float ssel[32];
    int r = blockIdx.x / 11;
    int chunk = blockIdx.x - r * 11;
    int tid = threadIdx.x;   // 64

    sb[tid]      = g_BINS[r * NB + tid];
    sb[tid + 64] = g_BINS[r * NB + 64 + tid];
    if (tid < 32) ssel[tid] = g_TB[r * 32 + tid];
    __syncthreads();

    int i = chunk * 64 + tid;
    float a = g_X0[r * HW + i];
    float2 rp = g_ROW[r];
    float lo = rp.x, W = rp.y;

    bool pos = (a >= 0.f);
    float msc = pos ? a * ssel[0] : a * ssel[16];   // max score exponent
    float nm = -msc;
    int mask = pos ? (NB - 1) : 0;
    float cs = pos ? fmaf((float)NB - 0.5f, W, lo) : fmaf(0.5f, W, lo);

    float rho = ex2(-fabsf(a) * W);                 // <= 1, decaying chain
    float rho4 = rho * rho; rho4 *= rho4;
    float p0 = ex2(fmaf(a, cs, nm));
    float p1 = p0 * rho, p2 = p1 * rho, p3 = p2 * rho;
    float L = a * LN2F;

    float D0 = 0.f, D1 = 0.f, D2 = 0.f, D3 = 0.f;
#pragma unroll 4
    for (int m = 0; m < NB; m += 4) {
        float4 c0 = sb[(m + 0) ^ mask];
        float4 c1 = sb[(m + 1) ^ mask];
        float4 c2 = sb[(m + 2) ^ mask];
        float4 c3 = sb[(m + 3) ^ mask];
        D0 = fmaf(p0, fmaf(L, fmaf(L, fmaf(L, c0.w, c0.z), c0.y), c0.x), D0);
        D1 = fmaf(p1, fmaf(L, fmaf(L, fmaf(L, c1.w, c1.z), c1.y), c1.x), D1);
        D2 = fmaf(p2, fmaf(L, fmaf(L, fmaf(L, c2.w, c2.z), c2.y), c2.x), D2);
        D3 = fmaf(p3, fmaf(L, fmaf(L, fmaf(L, c3.w, c3.z), c3.y), c3.x), D3);
        p0 *= rho4; p1 *= rho4; p2 *= rho4; p3 *= rho4;
    }
    float rD = __frcp_rn((D0 + D1) + (D2 + D3));

    const float* sel = pos ? ssel : (ssel + 16);
    float v[TOPK];
#pragma unroll
    for (int k = 0; k < TOPK; k++)
        v[k] = ex2(fmaf(a, sel[k], nm)) * rD;

    // output: idx = i*16 + k ; k2 = i/44 (k-independent)
    int n  = r / (S_FR - 1);
    int sp = r - n * (S_FR - 1);
    int k2 = i / 44;
    int im = i - k2 * 44;
    float4* o = reinterpret_cast<float4*>(
        out + ((size_t)((n * TOPK + k2) * (S_FR - 1) + sp)) * HW + im * 16);
    o[0] = make_float4(v[0],  v[1],  v[2],  v[3]);
    o[1] = make_float4(v[4],  v[5],  v[6],  v[7]);
    o[2] = make_float4(v[8],  v[9],  v[10], v[11]);
    o[3] = make_float4(v[12], v[13], v[14], v[15]);
}

// ---------------------------------------------------------------------------
extern "C" void kernel_launch(void* const* d_in, const int* in_sizes, int n_in,
                              void* d_out, int out_size) {
    const float* x  = (const float*)d_in[0];
    const float* w1 = (const float*)d_in[1];
    const float* b1 = (const float*)d_in[2];
    const float* w2 = (const float*)d_in[3];
    const float* b2 = (const float*)d_in[4];
    float* out = (float*)d_out;

    kA<<<NPIX / 64, 128>>>(x, w1, b1, w2, b2);
    kB<<<NS, 512>>>();
    kC<<<NS * 11, 64>>>(out);
}